// round 1
// baseline (speedup 1.0000x reference)
#include <cuda_runtime.h>
#include <cuda_bf16.h>
#include <cstddef>

// ---------------------------------------------------------------------------
// Scratch (static device memory — no allocations anywhere)
// ---------------------------------------------------------------------------
__device__ float g_x1[32u * 8192u * 32u];    // stage0 out (B, 8192, 32)
__device__ float g_x2[32u * 2048u * 64u];    // stage1 out (B, 2048, 64)
__device__ float g_x3[32u * 512u * 128u];    // stage2 out (B, 512, 128)
__device__ float g_x4[32u * 128u * 256u];    // stage3 out (B, 128, 256) == flat (32, 32768)
__device__ float g_part[16u * 32u * 512u];   // fc1 k-split partials
__device__ float g_h[32u * 512u];            // elu(fc1) activations

// ---------------------------------------------------------------------------
// Fused spiral_conv + ELU + mesh_pool.
// One block per output vertex v. 256 threads: tx = t&31 (channel lane),
// ty = t>>5 (batch group). Each thread owns TB=4 batches x TC=COUT/32 chans.
// For each of the 3 pooling parents: gather g (32 x FAN) chunk-wise into smem,
// stage W chunk in smem, FMA-accumulate, then ELU * dw -> output accumulator.
// ---------------------------------------------------------------------------
template<int CIN, int COUT, int KC>
__global__ void __launch_bounds__(256) stage_fused(
    const float* __restrict__ xin,     // (32, Vin, CIN)
    const int*   __restrict__ spiral,  // (Vin, 12)
    const int*   __restrict__ didx,    // (Vout, 3)
    const float* __restrict__ dw,      // (Vout, 3)
    const float* __restrict__ W,       // (12*CIN, COUT)
    const float* __restrict__ bias,    // (COUT)
    float* __restrict__ xout,          // (32, Vout, COUT)
    int Vin, int Vout)
{
    constexpr int S   = 12;
    constexpr int FAN = S * CIN;
    constexpr int TB  = 4;
    constexpr int TC  = COUT / 32;

    extern __shared__ float sm[];
    float* Ws = sm;                 // [KC][COUT]
    float* gs = sm + KC * COUT;     // [32][KC]
    __shared__ int sidx[S];

    const int v  = blockIdx.x;
    const int t  = threadIdx.x;
    const int tx = t & 31;
    const int ty = t >> 5;

    float outacc[TB][TC];
#pragma unroll
    for (int ib = 0; ib < TB; ++ib)
#pragma unroll
        for (int ic = 0; ic < TC; ++ic) outacc[ib][ic] = 0.f;

    for (int k = 0; k < 3; ++k) {
        const int   p  = didx[v * 3 + k];
        const float wk = dw[v * 3 + k];
        if (t < S) sidx[t] = spiral[p * S + t];
        __syncthreads();

        float acc[TB][TC];
#pragma unroll
        for (int ic = 0; ic < TC; ++ic) {
            const float bv = bias[tx + ic * 32];
#pragma unroll
            for (int ib = 0; ib < TB; ++ib) acc[ib][ic] = bv;
        }

        for (int j0 = 0; j0 < FAN; j0 += KC) {
            // stage W chunk
            for (int i = t; i < KC * COUT; i += 256)
                Ws[i] = W[(size_t)(j0 + i / COUT) * COUT + (i % COUT)];
            // gather g chunk
            for (int i = t; i < 32 * KC; i += 256) {
                const int bb = i / KC;
                const int j  = i % KC;
                const int jj = j0 + j;
                const int s  = jj / CIN;
                const int ci = jj % CIN;
                gs[i] = xin[(size_t)bb * Vin * CIN + (size_t)sidx[s] * CIN + ci];
            }
            __syncthreads();

#pragma unroll 4
            for (int j = 0; j < KC; ++j) {
                float wv[TC];
#pragma unroll
                for (int ic = 0; ic < TC; ++ic) wv[ic] = Ws[j * COUT + tx + ic * 32];
#pragma unroll
                for (int ib = 0; ib < TB; ++ib) {
                    const float gv = gs[(ty * TB + ib) * KC + j];
#pragma unroll
                    for (int ic = 0; ic < TC; ++ic)
                        acc[ib][ic] = fmaf(gv, wv[ic], acc[ib][ic]);
                }
            }
            __syncthreads();
        }

        // ELU then weighted pool accumulate
#pragma unroll
        for (int ib = 0; ib < TB; ++ib)
#pragma unroll
            for (int ic = 0; ic < TC; ++ic) {
                float a = acc[ib][ic];
                a = (a > 0.f) ? a : (__expf(a) - 1.f);
                outacc[ib][ic] = fmaf(wk, a, outacc[ib][ic]);
            }
    }

#pragma unroll
    for (int ib = 0; ib < TB; ++ib) {
        const int bb = ty * TB + ib;
#pragma unroll
        for (int ic = 0; ic < TC; ++ic)
            xout[(size_t)bb * Vout * COUT + (size_t)v * COUT + tx + ic * 32] = outacc[ib][ic];
    }
}

// ---------------------------------------------------------------------------
// FC1: (32, 32768) @ (32768, 512). Grid (16 c-tiles of 32, 16 k-splits of 2048).
// Deterministic: partials go to g_part, reduced afterwards.
// ---------------------------------------------------------------------------
__global__ void __launch_bounds__(256) fc1_partial(
    const float* __restrict__ xflat,   // (32, 32768) == g_x4
    const float* __restrict__ Wl1,     // (32768, 512)
    float* __restrict__ part)          // (16, 32, 512)
{
    extern __shared__ float sm[];
    float* xs = sm;           // [32][256]
    float* Ws = sm + 32 * 256; // [256][32]

    const int ct = blockIdx.x;     // c tile (32 wide)
    const int ks = blockIdx.y;     // k split (2048 wide)
    const int t  = threadIdx.x;
    const int tx = t & 31;
    const int ty = t >> 5;
    const int k0 = ks * 2048;

    float acc[4] = {0.f, 0.f, 0.f, 0.f};

    for (int kk0 = 0; kk0 < 2048; kk0 += 256) {
        for (int i = t; i < 32 * 256; i += 256) {
            const int bb = i >> 8, kk = i & 255;
            xs[i] = xflat[(size_t)bb * 32768 + k0 + kk0 + kk];
        }
        for (int i = t; i < 256 * 32; i += 256) {
            const int kk = i >> 5, cc = i & 31;
            Ws[i] = Wl1[(size_t)(k0 + kk0 + kk) * 512 + ct * 32 + cc];
        }
        __syncthreads();
#pragma unroll 4
        for (int kk = 0; kk < 256; ++kk) {
            const float wv = Ws[kk * 32 + tx];
#pragma unroll
            for (int ib = 0; ib < 4; ++ib)
                acc[ib] = fmaf(xs[(ty * 4 + ib) * 256 + kk], wv, acc[ib]);
        }
        __syncthreads();
    }

#pragma unroll
    for (int ib = 0; ib < 4; ++ib)
        part[(size_t)ks * 16384 + (size_t)(ty * 4 + ib) * 512 + ct * 32 + tx] = acc[ib];
}

__global__ void fc1_reduce(const float* __restrict__ part,
                           const float* __restrict__ bl1,
                           float* __restrict__ h,
                           float* __restrict__ out)
{
    const int i = blockIdx.x * 256 + threadIdx.x;  // 16384 = 32*512
    if (i < 16384) {
        float s = 0.f;
#pragma unroll
        for (int p = 0; p < 16; ++p) s += part[p * 16384 + i];
        s += bl1[i & 511];
        s = (s > 0.f) ? s : (__expf(s) - 1.f);
        h[i]   = s;
        out[i] = s;   // first output: elu(fc1) activations, (32, 512)
    }
}

__global__ void fc2_kernel(const float* __restrict__ h,
                           const float* __restrict__ Wl2,
                           const float* __restrict__ bl2,
                           float* __restrict__ out)
{
    const int b = blockIdx.x;      // 32
    const int c = threadIdx.x;     // 64
    float acc = bl2[c];
    for (int k = 0; k < 512; ++k)
        acc = fmaf(h[b * 512 + k], Wl2[k * 64 + c], acc);
    out[16384 + b * 64 + c] = acc; // second output: (32, 64)
}

// ---------------------------------------------------------------------------
// Host launcher
// ---------------------------------------------------------------------------
extern "C" void kernel_launch(void* const* d_in, const int* in_sizes, int n_in,
                              void* d_out, int out_size)
{
    // Input order detection:
    //   dict order      : x, [spiral_i, didx_i, dw_i, W_i, b_i] x4, Wl1, bl1, Wl2, bl2
    //   signature order : x, spiral0..3, didx0..3, dw0..3, W0,b0..W3,b3, Wl1, bl1, Wl2, bl2
    // Discriminator: in_sizes[2] == 24576 (didx0, dict) vs 98304 (spiral1, sig).
    int I_sp[4], I_di[4], I_dw[4], I_W[4], I_b[4];
    const int I_x = 0;
    int I_Wl1, I_bl1, I_Wl2, I_bl2;
    if (in_sizes[2] == 8192 * 3) {           // dict order
        for (int i = 0; i < 4; ++i) {
            I_sp[i] = 1 + 5 * i;
            I_di[i] = 2 + 5 * i;
            I_dw[i] = 3 + 5 * i;
            I_W[i]  = 4 + 5 * i;
            I_b[i]  = 5 + 5 * i;
        }
        I_Wl1 = 21; I_bl1 = 22; I_Wl2 = 23; I_bl2 = 24;
    } else {                                  // reference-signature order
        for (int i = 0; i < 4; ++i) {
            I_sp[i] = 1 + i;
            I_di[i] = 5 + i;
            I_dw[i] = 9 + i;
            I_W[i]  = 13 + 2 * i;
            I_b[i]  = 14 + 2 * i;
        }
        I_Wl1 = 21; I_bl1 = 22; I_Wl2 = 23; I_bl2 = 24;
    }

    const float* x   = (const float*)d_in[I_x];
    const int*   sp[4]; const int* di[4]; const float* dw[4];
    const float* W[4]; const float* b[4];
    for (int i = 0; i < 4; ++i) {
        sp[i] = (const int*)  d_in[I_sp[i]];
        di[i] = (const int*)  d_in[I_di[i]];
        dw[i] = (const float*)d_in[I_dw[i]];
        W[i]  = (const float*)d_in[I_W[i]];
        b[i]  = (const float*)d_in[I_b[i]];
    }
    const float* Wl1 = (const float*)d_in[I_Wl1];
    const float* bl1 = (const float*)d_in[I_bl1];
    const float* Wl2 = (const float*)d_in[I_Wl2];
    const float* bl2 = (const float*)d_in[I_bl2];

    float *x1, *x2, *x3, *x4, *part, *h;
    cudaGetSymbolAddress((void**)&x1,   g_x1);
    cudaGetSymbolAddress((void**)&x2,   g_x2);
    cudaGetSymbolAddress((void**)&x3,   g_x3);
    cudaGetSymbolAddress((void**)&x4,   g_x4);
    cudaGetSymbolAddress((void**)&part, g_part);
    cudaGetSymbolAddress((void**)&h,    g_h);

    float* out = (float*)d_out;

    // Dynamic smem sizes
    const int sm0 = (36 * 32  + 32 * 36 ) * 4;   //  9216 B
    const int sm1 = (128 * 64 + 32 * 128) * 4;   // 49152 B
    const int sm2 = (128 * 128 + 32 * 128) * 4;  // 81920 B
    const int sm3 = (128 * 256 + 32 * 128) * 4;  // 147456 B
    const int smf = (32 * 256 + 256 * 32) * 4;   // 65536 B

    cudaFuncSetAttribute(stage_fused<3,   32, 36 >, cudaFuncAttributeMaxDynamicSharedMemorySize, sm0);
    cudaFuncSetAttribute(stage_fused<32,  64, 128>, cudaFuncAttributeMaxDynamicSharedMemorySize, sm1);
    cudaFuncSetAttribute(stage_fused<64, 128, 128>, cudaFuncAttributeMaxDynamicSharedMemorySize, sm2);
    cudaFuncSetAttribute(stage_fused<128,256, 128>, cudaFuncAttributeMaxDynamicSharedMemorySize, sm3);
    cudaFuncSetAttribute(fc1_partial,               cudaFuncAttributeMaxDynamicSharedMemorySize, smf);

    stage_fused<3,   32, 36 ><<<8192, 256, sm0>>>(x,  sp[0], di[0], dw[0], W[0], b[0], x1, 32768, 8192);
    stage_fused<32,  64, 128><<<2048, 256, sm1>>>(x1, sp[1], di[1], dw[1], W[1], b[1], x2, 8192,  2048);
    stage_fused<64, 128, 128><<<512,  256, sm2>>>(x2, sp[2], di[2], dw[2], W[2], b[2], x3, 2048,  512);
    stage_fused<128,256, 128><<<128,  256, sm3>>>(x3, sp[3], di[3], dw[3], W[3], b[3], x4, 512,   128);

    fc1_partial<<<dim3(16, 16), 256, smf>>>(x4, Wl1, part);
    fc1_reduce <<<64, 256>>>(part, bl1, h, out);
    fc2_kernel <<<32, 64>>>(h, Wl2, bl2, out);
}

// round 2
// speedup vs baseline: 1.2990x; 1.2990x over previous
#include <cuda_runtime.h>
#include <cstddef>

typedef unsigned long long ull;

// ---------------------------------------------------------------------------
// Scratch (static device memory — no allocations anywhere)
// ---------------------------------------------------------------------------
__device__ float g_x1[32u * 8192u * 32u];     // stage0 out (B, 8192, 32)
__device__ float g_x2[32u * 2048u * 64u];     // stage1 out
__device__ float g_x3[32u * 512u * 128u];     // stage2 out
__device__ float g_x4[32u * 128u * 256u];     // stage3 out == flat (32, 32768)
__device__ float g_p0[8192u * 3u * 32u * 32u];   // per-(v,k) partials
__device__ float g_p1[2048u * 3u * 32u * 64u];
__device__ float g_p2[512u  * 3u * 32u * 128u];
__device__ float g_p3[128u  * 3u * 32u * 256u];
__device__ float g_pf[64u * 32u * 512u];      // fc1 k-split partials
__device__ float g_h[32u * 512u];             // elu(fc1)

// ---------------------------------------------------------------------------
// f32x2 packed helpers
// ---------------------------------------------------------------------------
__device__ __forceinline__ ull pack2(float lo, float hi) {
    ull r; asm("mov.b64 %0, {%1, %2};" : "=l"(r) : "f"(lo), "f"(hi)); return r;
}
__device__ __forceinline__ void unpack2(ull v, float& lo, float& hi) {
    asm("mov.b64 {%0, %1}, %2;" : "=f"(lo), "=f"(hi) : "l"(v));
}
__device__ __forceinline__ void fma2(ull& d, ull a, ull b) {
    asm("fma.rn.f32x2 %0, %1, %2, %0;" : "+l"(d) : "l"(a), "l"(b));
}
__device__ __forceinline__ float elu_f(float a) {
    return (a > 0.f) ? a : (__expf(a) - 1.f);
}

// ---------------------------------------------------------------------------
// Fused spiral_conv (+bias, ELU, *dw) for ONE (vertex, parent) pair per
// instance. Block = 256 threads = VSUB instances of COUT threads each.
// Instance layout: LANES = COUT/4 lanes (tx) x 4 pair-groups (pg).
// Thread owns TC=4 consecutive couts (c = 4*tx+ic) x TBP=4 batch-pairs
// (batches 2*pp, 2*pp+1 with pp = pg*4+ibp)  ->  16 f32x2 accumulators.
// ---------------------------------------------------------------------------
template<int CIN, int COUT, int KC, int VSUB>
__global__ void __launch_bounds__(256, 2) stage_conv(
    const float* __restrict__ xin,     // (32, Vin, CIN)
    const int*   __restrict__ spiral,  // (Vin, 12)
    const int*   __restrict__ didx,    // (Vout, 3)
    const float* __restrict__ dw,      // (Vout, 3)
    const float* __restrict__ W,       // (12*CIN, COUT)
    const float* __restrict__ bias,    // (COUT)
    float* __restrict__ part,          // (Vout*3, 32, COUT)
    int Vin, int Vout)
{
    constexpr int S     = 12;
    constexpr int FAN   = S * CIN;
    constexpr int LANES = COUT / 4;
    constexpr int GSROW = 34;                 // 32 batches + pad (keeps 8B align, 2-way wr conflict)
    constexpr int GSZ   = KC * GSROW;
    constexpr int E     = (VSUB * KC * 32) / 256;

    extern __shared__ float sm[];
    float* Ws = sm;                 // [KC][COUT]
    float* gs = sm + KC * COUT;     // [VSUB][KC][GSROW]
    __shared__ int   s_sidx[VSUB][S];
    __shared__ float s_wk[VSUB];

    const int t    = threadIdx.x;
    const int inst = t / COUT;
    const int ti   = t % COUT;
    const int tx   = ti % LANES;
    const int pg   = ti / LANES;
    const int vk0  = blockIdx.x * VSUB;

    if (t < VSUB * S) {
        const int i2 = t / S, s = t % S;
        const int vk = vk0 + i2;
        const int v  = vk / 3, k = vk % 3;
        const int p  = didx[v * 3 + k];
        s_sidx[i2][s] = spiral[p * S + s];
        if (s == 0) s_wk[i2] = dw[v * 3 + k];
    }

    // init accumulators with bias
    ull acc[4][4];
    {
        const float4 bv = *(const float4*)&bias[tx * 4];
#pragma unroll
        for (int ibp = 0; ibp < 4; ++ibp) {
            acc[0][ibp] = pack2(bv.x, bv.x);
            acc[1][ibp] = pack2(bv.y, bv.y);
            acc[2][ibp] = pack2(bv.z, bv.z);
            acc[3][ibp] = pack2(bv.w, bv.w);
        }
    }
    __syncthreads();

    for (int j0 = 0; j0 < FAN; j0 += KC) {
        // stage W chunk (straight vectorized copy)
        {
            const float4* src = (const float4*)(W + (size_t)j0 * COUT);
            float4* dst = (float4*)Ws;
            for (int i = t; i < KC * COUT / 4; i += 256) dst[i] = src[i];
        }
        // stage gathered g chunk: gs[inst][jj][b]
#pragma unroll
        for (int e = 0; e < E; ++e) {
            const int idx = t * E + e;
            const int ig  = idx / (32 * KC);
            const int r   = idx % (32 * KC);
            const int b   = r / KC;
            const int jj  = r % KC;
            const int j   = j0 + jj;
            const int s   = j / CIN;
            const int ci  = j % CIN;
            gs[ig * GSZ + jj * GSROW + b] =
                xin[(size_t)b * Vin * CIN + (size_t)s_sidx[ig][s] * CIN + ci];
        }
        __syncthreads();

        const float* gb = gs + inst * GSZ + pg * 8;
#pragma unroll 4
        for (int jj = 0; jj < KC; ++jj) {
            const float4 w4 = *(const float4*)&Ws[jj * COUT + tx * 4];
            ull wp[4];
            wp[0] = pack2(w4.x, w4.x);
            wp[1] = pack2(w4.y, w4.y);
            wp[2] = pack2(w4.z, w4.z);
            wp[3] = pack2(w4.w, w4.w);
            ull gp[4];
#pragma unroll
            for (int ibp = 0; ibp < 4; ++ibp)
                gp[ibp] = *(const ull*)&gb[jj * GSROW + 2 * ibp];
#pragma unroll
            for (int ic = 0; ic < 4; ++ic)
#pragma unroll
                for (int ibp = 0; ibp < 4; ++ibp)
                    fma2(acc[ic][ibp], gp[ibp], wp[ic]);
        }
        __syncthreads();
    }

    // epilogue: ELU, * dw, store two batches per pair
    const float wk = s_wk[inst];
    const size_t base = ((size_t)(vk0 + inst) * 32) * COUT + tx * 4;
#pragma unroll
    for (int ibp = 0; ibp < 4; ++ibp) {
        const int b0 = (pg * 4 + ibp) * 2;
        float lo[4], hi[4];
#pragma unroll
        for (int ic = 0; ic < 4; ++ic) {
            unpack2(acc[ic][ibp], lo[ic], hi[ic]);
            lo[ic] = wk * elu_f(lo[ic]);
            hi[ic] = wk * elu_f(hi[ic]);
        }
        *(float4*)&part[base + (size_t)b0 * COUT]       = make_float4(lo[0], lo[1], lo[2], lo[3]);
        *(float4*)&part[base + (size_t)(b0 + 1) * COUT] = make_float4(hi[0], hi[1], hi[2], hi[3]);
    }
}

// ---------------------------------------------------------------------------
// Pool-reduce: xout[b][v][c] = sum_k part[v*3+k][b][c]
// ---------------------------------------------------------------------------
template<int COUT>
__global__ void reduce_pool(const float* __restrict__ part,
                            float* __restrict__ xout, int Vout, int total4)
{
    const int i = blockIdx.x * 256 + threadIdx.x;
    if (i >= total4) return;
    constexpr int C4 = COUT / 4;
    const int c4 = i % C4;
    const int v  = (i / C4) % Vout;
    const int b  = i / (C4 * Vout);
    const float4* p = (const float4*)part;
    float4 a0 = p[((size_t)(v * 3 + 0) * 32 + b) * C4 + c4];
    float4 a1 = p[((size_t)(v * 3 + 1) * 32 + b) * C4 + c4];
    float4 a2 = p[((size_t)(v * 3 + 2) * 32 + b) * C4 + c4];
    float4 o = make_float4(a0.x + a1.x + a2.x, a0.y + a1.y + a2.y,
                           a0.z + a1.z + a2.z, a0.w + a1.w + a2.w);
    ((float4*)xout)[((size_t)b * Vout + v) * C4 + c4] = o;
}

// ---------------------------------------------------------------------------
// FC1 partial GEMM: (32, 32768) @ (32768, 512), grid (2 ctiles x 64 ksplits)
// Same inner pattern (CT=256, LANES=64, 4 pg, TC=4, TBP=4).
// ---------------------------------------------------------------------------
__global__ void __launch_bounds__(256, 2) fc1_conv(
    const float* __restrict__ xf,      // (32, 32768)
    const float* __restrict__ Wl1,     // (32768, 512)
    float* __restrict__ partf)         // (64, 32, 512)
{
    constexpr int KC = 64, CT = 256, LANES = 64, GSROW = 34;
    extern __shared__ float sm[];
    float* Ws = sm;                 // [KC][CT]
    float* xs = sm + KC * CT;       // [KC][GSROW]

    const int t   = threadIdx.x;
    const int tx  = t % LANES;
    const int pg  = t / LANES;
    const int ct0 = blockIdx.x * CT;
    const int k0  = blockIdx.y * 512;

    ull acc[4][4];
#pragma unroll
    for (int ic = 0; ic < 4; ++ic)
#pragma unroll
        for (int ibp = 0; ibp < 4; ++ibp) acc[ic][ibp] = 0ull;

    for (int kc = 0; kc < 512; kc += KC) {
        const int kk0 = k0 + kc;
        for (int i = t; i < KC * CT / 4; i += 256) {
            const int row = i / (CT / 4), col = i % (CT / 4);
            ((float4*)Ws)[i] = *(const float4*)&Wl1[(size_t)(kk0 + row) * 512 + ct0 + col * 4];
        }
#pragma unroll
        for (int e = 0; e < 8; ++e) {
            const int idx = t * 8 + e;
            const int b = idx / KC, jj = idx % KC;
            xs[jj * GSROW + b] = xf[(size_t)b * 32768 + kk0 + jj];
        }
        __syncthreads();

        const float* gb = xs + pg * 8;
#pragma unroll 4
        for (int jj = 0; jj < KC; ++jj) {
            const float4 w4 = *(const float4*)&Ws[jj * CT + tx * 4];
            ull wp[4];
            wp[0] = pack2(w4.x, w4.x);
            wp[1] = pack2(w4.y, w4.y);
            wp[2] = pack2(w4.z, w4.z);
            wp[3] = pack2(w4.w, w4.w);
            ull gp[4];
#pragma unroll
            for (int ibp = 0; ibp < 4; ++ibp)
                gp[ibp] = *(const ull*)&gb[jj * GSROW + 2 * ibp];
#pragma unroll
            for (int ic = 0; ic < 4; ++ic)
#pragma unroll
                for (int ibp = 0; ibp < 4; ++ibp)
                    fma2(acc[ic][ibp], gp[ibp], wp[ic]);
        }
        __syncthreads();
    }

    const size_t base = (size_t)blockIdx.y * 32 * 512 + ct0 + tx * 4;
#pragma unroll
    for (int ibp = 0; ibp < 4; ++ibp) {
        const int b0 = (pg * 4 + ibp) * 2;
        float lo[4], hi[4];
#pragma unroll
        for (int ic = 0; ic < 4; ++ic) unpack2(acc[ic][ibp], lo[ic], hi[ic]);
        *(float4*)&partf[base + (size_t)b0 * 512]       = make_float4(lo[0], lo[1], lo[2], lo[3]);
        *(float4*)&partf[base + (size_t)(b0 + 1) * 512] = make_float4(hi[0], hi[1], hi[2], hi[3]);
    }
}

__global__ void fc1_reduce(const float* __restrict__ partf,
                           const float* __restrict__ bl1,
                           float* __restrict__ h,
                           float* __restrict__ out)
{
    const int i = blockIdx.x * 256 + threadIdx.x;   // 16384 = 32*512
    if (i < 16384) {
        float s = 0.f;
#pragma unroll
        for (int p = 0; p < 64; ++p) s += partf[p * 16384 + i];
        s += bl1[i & 511];
        s = elu_f(s);
        h[i]   = s;
        out[i] = s;   // first output: elu(fc1), (32, 512)
    }
}

__global__ void fc2_kernel(const float* __restrict__ h,
                           const float* __restrict__ Wl2,
                           const float* __restrict__ bl2,
                           float* __restrict__ out)
{
    const int b = blockIdx.x;      // 32
    const int c = threadIdx.x;     // 64
    float acc = bl2[c];
    for (int k = 0; k < 512; ++k)
        acc = fmaf(h[b * 512 + k], Wl2[k * 64 + c], acc);
    out[16384 + b * 64 + c] = acc; // second output: (32, 64)
}

// ---------------------------------------------------------------------------
// Host launcher
// ---------------------------------------------------------------------------
extern "C" void kernel_launch(void* const* d_in, const int* in_sizes, int n_in,
                              void* d_out, int out_size)
{
    int I_sp[4], I_di[4], I_dw[4], I_W[4], I_b[4];
    int I_Wl1, I_bl1, I_Wl2, I_bl2;
    if (in_sizes[2] == 8192 * 3) {           // dict order
        for (int i = 0; i < 4; ++i) {
            I_sp[i] = 1 + 5 * i; I_di[i] = 2 + 5 * i; I_dw[i] = 3 + 5 * i;
            I_W[i] = 4 + 5 * i;  I_b[i] = 5 + 5 * i;
        }
        I_Wl1 = 21; I_bl1 = 22; I_Wl2 = 23; I_bl2 = 24;
    } else {                                  // signature order
        for (int i = 0; i < 4; ++i) {
            I_sp[i] = 1 + i; I_di[i] = 5 + i; I_dw[i] = 9 + i;
            I_W[i] = 13 + 2 * i; I_b[i] = 14 + 2 * i;
        }
        I_Wl1 = 21; I_bl1 = 22; I_Wl2 = 23; I_bl2 = 24;
    }

    const float* x = (const float*)d_in[0];
    const int* sp[4]; const int* di[4]; const float* dwp[4];
    const float* W[4]; const float* b[4];
    for (int i = 0; i < 4; ++i) {
        sp[i]  = (const int*)  d_in[I_sp[i]];
        di[i]  = (const int*)  d_in[I_di[i]];
        dwp[i] = (const float*)d_in[I_dw[i]];
        W[i]   = (const float*)d_in[I_W[i]];
        b[i]   = (const float*)d_in[I_b[i]];
    }
    const float* Wl1 = (const float*)d_in[I_Wl1];
    const float* bl1 = (const float*)d_in[I_bl1];
    const float* Wl2 = (const float*)d_in[I_Wl2];
    const float* bl2 = (const float*)d_in[I_bl2];

    float *x1, *x2, *x3, *x4, *p0, *p1, *p2, *p3, *pf, *h;
    cudaGetSymbolAddress((void**)&x1, g_x1);
    cudaGetSymbolAddress((void**)&x2, g_x2);
    cudaGetSymbolAddress((void**)&x3, g_x3);
    cudaGetSymbolAddress((void**)&x4, g_x4);
    cudaGetSymbolAddress((void**)&p0, g_p0);
    cudaGetSymbolAddress((void**)&p1, g_p1);
    cudaGetSymbolAddress((void**)&p2, g_p2);
    cudaGetSymbolAddress((void**)&p3, g_p3);
    cudaGetSymbolAddress((void**)&pf, g_pf);
    cudaGetSymbolAddress((void**)&h,  g_h);
    float* out = (float*)d_out;

    const int sm0 = (36 * 32  + 8 * 36 * 34) * 4;  // 43776
    const int sm1 = (64 * 64  + 4 * 64 * 34) * 4;  // 51200
    const int sm2 = (64 * 128 + 2 * 64 * 34) * 4;  // 50176
    const int sm3 = (64 * 256 + 1 * 64 * 34) * 4;  // 74240
    const int smf = (64 * 256 + 64 * 34) * 4;      // 74240

    cudaFuncSetAttribute(stage_conv<3,  32, 36, 8>, cudaFuncAttributeMaxDynamicSharedMemorySize, sm0);
    cudaFuncSetAttribute(stage_conv<32, 64, 64, 4>, cudaFuncAttributeMaxDynamicSharedMemorySize, sm1);
    cudaFuncSetAttribute(stage_conv<64,128, 64, 2>, cudaFuncAttributeMaxDynamicSharedMemorySize, sm2);
    cudaFuncSetAttribute(stage_conv<128,256,64, 1>, cudaFuncAttributeMaxDynamicSharedMemorySize, sm3);
    cudaFuncSetAttribute(fc1_conv,                  cudaFuncAttributeMaxDynamicSharedMemorySize, smf);

    stage_conv<3,  32, 36, 8><<<3072, 256, sm0>>>(x,  sp[0], di[0], dwp[0], W[0], b[0], p0, 32768, 8192);
    reduce_pool<32><<<8192, 256>>>(p0, x1, 8192, 32 * 8192 * 8);

    stage_conv<32, 64, 64, 4><<<1536, 256, sm1>>>(x1, sp[1], di[1], dwp[1], W[1], b[1], p1, 8192, 2048);
    reduce_pool<64><<<4096, 256>>>(p1, x2, 2048, 32 * 2048 * 16);

    stage_conv<64,128, 64, 2><<<768, 256, sm2>>>(x2, sp[2], di[2], dwp[2], W[2], b[2], p2, 2048, 512);
    reduce_pool<128><<<2048, 256>>>(p2, x3, 512, 32 * 512 * 32);

    stage_conv<128,256,64, 1><<<384, 256, sm3>>>(x3, sp[3], di[3], dwp[3], W[3], b[3], p3, 512, 128);
    reduce_pool<256><<<1024, 256>>>(p3, x4, 128, 32 * 128 * 64);

    fc1_conv<<<dim3(2, 64), 256, smf>>>(x4, Wl1, pf);
    fc1_reduce<<<64, 256>>>(pf, bl1, h, out);
    fc2_kernel<<<32, 64>>>(h, Wl2, bl2, out);
}